// round 11
// baseline (speedup 1.0000x reference)
#include <cuda_runtime.h>
#include <cuda_fp16.h>
#include <cstdint>
#include <cstddef>

#define N_NODES 50000
#define N_EDGES 800000
#define EDGE_F 96
#define NODE_F 256
#define GLOB_F 64
#define HIDDEN 1024
#define MLP_K 544            // K for GEMM1 after hoisting the u-term
#define N_GRAPHS 8
#define CAP 128

// ---------------- scratch (static device globals; no allocations) ------------
__device__ int    g_cnt[N_NODES];
__device__ int    g_bucket[N_NODES * CAP];
__device__ __half g_h[(size_t)N_NODES * MLP_K];      // fp16 MLP input (544 feats)
__device__ __half g_hid[(size_t)N_NODES * HIDDEN];   // fp16 hidden
__device__ __half g_w1t[HIDDEN * MLP_K];             // W1[0:544]^T fp16  [n][k]
__device__ __half g_w2t[NODE_F * HIDDEN];            // W2^T fp16  [n][k]
__device__ float  g_ug[N_GRAPHS * HIDDEN];           // b1 + u @ W1[544:608]

// ---------------- merged prep kernel ----------------------------------------
#define ZB 196
#define W1TB (ZB + 544)
#define W2TB (W1TB + 256)
#define PREPB (W2TB + 32)

__global__ void k_prep(const float* __restrict__ W1, const float* __restrict__ W2,
                       const float* __restrict__ u, const float* __restrict__ b1) {
    int b = blockIdx.x;
    int t = threadIdx.x;
    if (b < ZB) {                               // ---- zero counts
        int i = b * 256 + t;
        if (i < N_NODES) g_cnt[i] = 0;
        return;
    }
    if (b < W2TB) {                             // ---- tiled transposes
        __shared__ float tile[32][33];
        bool isW1 = (b < W1TB);
        int tb = isW1 ? (b - ZB) : (b - W1TB);
        int ntiles_n = isW1 ? 32 : 8;
        int K = isW1 ? MLP_K : HIDDEN;
        int N = isW1 ? HIDDEN : NODE_F;
        const float* W = isW1 ? W1 : W2;
        __half* Wt = isW1 ? g_w1t : g_w2t;
        int k0 = (tb / ntiles_n) * 32;
        int n0 = (tb % ntiles_n) * 32;
        int r = t >> 5, c = t & 31;
#pragma unroll
        for (int p = 0; p < 4; p++)
            tile[r + 8 * p][c] = W[(size_t)(k0 + r + 8 * p) * N + n0 + c];
        __syncthreads();
        int r2 = t >> 4, c2 = (t & 15) * 2;
#pragma unroll
        for (int p = 0; p < 2; p++) {
            int nn = r2 + 16 * p;
            __half2 v = __floats2half2_rn(tile[c2][nn], tile[c2 + 1][nn]);
            *(__half2*)(Wt + (size_t)(n0 + nn) * K + k0 + c2) = v;
        }
        return;
    }
    {                                           // ---- ug table
        int idx = (b - W2TB) * 256 + t;
        int g = idx >> 10, n = idx & (HIDDEN - 1);
        float s = b1[n];
#pragma unroll 8
        for (int j = 0; j < GLOB_F; j++)
            s += u[g * GLOB_F + j] * W1[(size_t)(MLP_K + j) * HIDDEN + n];
        g_ug[idx] = s;
    }
}

__global__ void k_scatter(const int* __restrict__ col) {
    int e = blockIdx.x * blockDim.x + threadIdx.x;
    if (e >= N_EDGES) return;
    int c = col[e];
    int p = atomicAdd(&g_cnt[c], 1);
    if (p < CAP) g_bucket[c * CAP + p] = e;
}

// warp-per-node gather-reduce with 8-wide index prefetch; fp16 h row output
__global__ void k_gather(const float* __restrict__ x, const float* __restrict__ ea) {
    int node = blockIdx.x * 8 + (threadIdx.x >> 5);
    if (node >= N_NODES) return;
    int lane = threadIdx.x & 31;
    int deg = g_cnt[node];
    if (deg > CAP) deg = CAP;
    const float NEG = __int_as_float(0xff800000);
    float s0 = 0.f, s1 = 0.f, s2 = 0.f;
    float m0 = NEG, m1 = NEG, m2 = NEG;
    const int* bk = g_bucket + node * CAP;

    int j = 0;
    for (; j + 8 <= deg; j += 8) {
        const float* p[8];
#pragma unroll
        for (int q = 0; q < 8; q++) p[q] = ea + (size_t)bk[j + q] * EDGE_F;
        float v0[8], v1[8], v2[8];
#pragma unroll
        for (int q = 0; q < 8; q++) {
            v0[q] = p[q][lane]; v1[q] = p[q][lane + 32]; v2[q] = p[q][lane + 64];
        }
#pragma unroll
        for (int q = 0; q < 8; q++) {
            s0 += v0[q]; m0 = fmaxf(m0, v0[q]);
            s1 += v1[q]; m1 = fmaxf(m1, v1[q]);
            s2 += v2[q]; m2 = fmaxf(m2, v2[q]);
        }
    }
    for (; j < deg; j++) {
        const float* r = ea + (size_t)bk[j] * EDGE_F;
        float v0 = r[lane], v1 = r[lane + 32], v2 = r[lane + 64];
        s0 += v0; m0 = fmaxf(m0, v0);
        s1 += v1; m1 = fmaxf(m1, v1);
        s2 += v2; m2 = fmaxf(m2, v2);
    }
    if (deg == 0) { m0 = 0.f; m1 = 0.f; m2 = 0.f; }
    float inv = deg ? 1.f / (float)deg : 0.f;

    __half* h = g_h + (size_t)node * MLP_K;
    const float* xr = x + (size_t)node * NODE_F;
#pragma unroll
    for (int i = 0; i < 8; i++) h[lane + 32 * i] = __float2half_rn(xr[lane + 32 * i]);
    h[256 + lane] = __float2half_rn(s0);
    h[288 + lane] = __float2half_rn(s1);
    h[320 + lane] = __float2half_rn(s2);
    h[352 + lane] = __float2half_rn(m0);
    h[384 + lane] = __float2half_rn(m1);
    h[416 + lane] = __float2half_rn(m2);
    h[448 + lane] = __float2half_rn(s0 * inv);
    h[480 + lane] = __float2half_rn(s1 * inv);
    h[512 + lane] = __float2half_rn(s2 * inv);
}

// ------- fp16 GEMM: CTA 128x256, warp 64x64, m16n8k16 + ldmatrix, 3-stage ----
#define BM 128
#define BN 256
#define BK 32
#define ROWB 80
#define A_TILE (BM * ROWB)          // 10240 B
#define B_TILE (BN * ROWB)          // 20480 B
#define STAGE_B (A_TILE + B_TILE)   // 30720 B
#define NSTG 3

__device__ __forceinline__ void cp16(uint32_t dst, const void* src, int sz) {
    asm volatile("cp.async.cg.shared.global [%0], [%1], 16, %2;\n"
                 :: "r"(dst), "l"(src), "r"(sz));
}

__device__ __forceinline__ void ldsm4(uint32_t* r, uint32_t addr) {
    asm volatile("ldmatrix.sync.aligned.m8n8.x4.shared.b16 {%0,%1,%2,%3}, [%4];"
                 : "=r"(r[0]), "=r"(r[1]), "=r"(r[2]), "=r"(r[3]) : "r"(addr));
}

template <bool FIRST>
__global__ void __launch_bounds__(256, 1)
k_gemm(const __half* __restrict__ A, const __half* __restrict__ Bw,
       const float* __restrict__ bias,           // GEMM2: b2 ; GEMM1: unused
       const float* __restrict__ ug,             // GEMM1: per-graph table
       const int* __restrict__ batch,            // GEMM1: node -> graph
       const float* __restrict__ resid,
       void* __restrict__ Cp, int M, int K, int N) {
    extern __shared__ char smc[];
    uint32_t smb = (uint32_t)__cvta_generic_to_shared(smc);
    int tid = threadIdx.x;
    int warp = tid >> 5, lane = tid & 31;
    int bm = blockIdx.y * BM;
    int bn = blockIdx.x * BN;
    int KT = K / BK;

    auto load = [&](int st, int kb) {
        uint32_t ab = smb + st * STAGE_B;
        uint32_t bb = ab + A_TILE;
#pragma unroll
        for (int i = 0; i < 2; i++) {             // A: 128 rows x 4 chunks
            int id = tid + i * 256;
            int r = id >> 2, c = id & 3;
            int gr = bm + r;
            const __half* srcA = A + (size_t)((gr < M) ? gr : 0) * K + kb * BK + c * 8;
            cp16(ab + r * ROWB + c * 16, srcA, (gr < M) ? 16 : 0);
        }
#pragma unroll
        for (int i = 0; i < 4; i++) {             // B: 256 rows x 4 chunks
            int id = tid + i * 256;
            int r = id >> 2, c = id & 3;
            const __half* srcB = Bw + (size_t)(bn + r) * K + kb * BK + c * 8;
            cp16(bb + r * ROWB + c * 16, srcB, 16);
        }
    };

    load(0, 0);
    asm volatile("cp.async.commit_group;\n");
    load(1, 1);
    asm volatile("cp.async.commit_group;\n");

    float acc[4][8][4];
#pragma unroll
    for (int a = 0; a < 4; a++)
#pragma unroll
        for (int b = 0; b < 8; b++)
#pragma unroll
            for (int c = 0; c < 4; c++) acc[a][b][c] = 0.f;

    int wm = (warp & 1) * 64, wn = (warp >> 1) * 64;
    int a_m = (lane & 7) + ((lane >> 3) & 1) * 8;
    int a_k8 = (lane >> 4) * 8;
    int b_n = lane & 7;
    int b_k8 = (lane >> 3) * 8;

    for (int kt = 0; kt < KT; kt++) {
        asm volatile("cp.async.wait_group 1;\n");
        __syncthreads();
        uint32_t ab = smb + (kt % NSTG) * STAGE_B;
        uint32_t bb = ab + A_TILE;

        uint32_t bF[8][4];
#pragma unroll
        for (int nt = 0; nt < 8; nt++)
            ldsm4(bF[nt], bb + (wn + nt * 8 + b_n) * ROWB + b_k8 * 2);

#pragma unroll
        for (int ks = 0; ks < 2; ks++) {
            uint32_t aF[4][4];
#pragma unroll
            for (int mt = 0; mt < 4; mt++)
                ldsm4(aF[mt], ab + (wm + mt * 16 + a_m) * ROWB + (ks * 16 + a_k8) * 2);
#pragma unroll
            for (int mt = 0; mt < 4; mt++)
#pragma unroll
                for (int nt = 0; nt < 8; nt++)
                    asm volatile(
                        "mma.sync.aligned.m16n8k16.row.col.f32.f16.f16.f32 "
                        "{%0,%1,%2,%3},{%4,%5,%6,%7},{%8,%9},{%0,%1,%2,%3};\n"
                        : "+f"(acc[mt][nt][0]), "+f"(acc[mt][nt][1]),
                          "+f"(acc[mt][nt][2]), "+f"(acc[mt][nt][3])
                        : "r"(aF[mt][0]), "r"(aF[mt][1]), "r"(aF[mt][2]), "r"(aF[mt][3]),
                          "r"(bF[nt][2 * ks]), "r"(bF[nt][2 * ks + 1]));
        }
        if (kt + 2 < KT) load((kt + 2) % NSTG, kt + 2);
        asm volatile("cp.async.commit_group;\n");
    }

    // ---------------- epilogue ----------------
    int lr = lane >> 2, lc = lane & 3;
#pragma unroll
    for (int mt = 0; mt < 4; mt++) {
        int rb = bm + wm + mt * 16 + lr;
        int row0 = rb, row1 = rb + 8;
        int g0 = 0, g1 = 0;
        if (FIRST) {
            g0 = (row0 < M) ? batch[row0] : 0;
            g1 = (row1 < M) ? batch[row1] : 0;
        }
#pragma unroll
        for (int nt = 0; nt < 8; nt++) {
            int cb = bn + wn + nt * 8 + 2 * lc;
            if (FIRST) {
                __half* C = (__half*)Cp;
                if (row0 < M) {
                    float2 t = *(const float2*)(ug + g0 * HIDDEN + cb);
                    float v0 = fmaxf(acc[mt][nt][0] + t.x, 0.f);
                    float v1 = fmaxf(acc[mt][nt][1] + t.y, 0.f);
                    *(__half2*)(C + (size_t)row0 * N + cb) = __floats2half2_rn(v0, v1);
                }
                if (row1 < M) {
                    float2 t = *(const float2*)(ug + g1 * HIDDEN + cb);
                    float v2 = fmaxf(acc[mt][nt][2] + t.x, 0.f);
                    float v3 = fmaxf(acc[mt][nt][3] + t.y, 0.f);
                    *(__half2*)(C + (size_t)row1 * N + cb) = __floats2half2_rn(v2, v3);
                }
            } else {
                float bx = bias[cb], by = bias[cb + 1];
                float* C = (float*)Cp;
                if (row0 < M) {
                    C[(size_t)row0 * N + cb]     = acc[mt][nt][0] + bx + resid[(size_t)row0 * N + cb];
                    C[(size_t)row0 * N + cb + 1] = acc[mt][nt][1] + by + resid[(size_t)row0 * N + cb + 1];
                }
                if (row1 < M) {
                    C[(size_t)row1 * N + cb]     = acc[mt][nt][2] + bx + resid[(size_t)row1 * N + cb];
                    C[(size_t)row1 * N + cb + 1] = acc[mt][nt][3] + by + resid[(size_t)row1 * N + cb + 1];
                }
            }
        }
    }
}

// ---------------- launch ------------------------------------------------------
extern "C" void kernel_launch(void* const* d_in, const int* in_sizes, int n_in,
                              void* d_out, int out_size) {
    const float* x  = (const float*)d_in[0];
    const float* ea = (const float*)d_in[1];
    const float* u  = (const float*)d_in[2];
    const float* W1 = (const float*)d_in[3];
    const float* b1 = (const float*)d_in[4];
    const float* W2 = (const float*)d_in[5];
    const float* b2 = (const float*)d_in[6];
    const int*   ei = (const int*)d_in[7];   // [2, N_EDGES] int32
    const int*   bt = (const int*)d_in[8];
    float* out = (float*)d_out;

    __half *pH, *pHid, *pW1t, *pW2t;
    float* pUg;
    cudaGetSymbolAddress((void**)&pH, g_h);
    cudaGetSymbolAddress((void**)&pHid, g_hid);
    cudaGetSymbolAddress((void**)&pW1t, g_w1t);
    cudaGetSymbolAddress((void**)&pW2t, g_w2t);
    cudaGetSymbolAddress((void**)&pUg, g_ug);

    const int smem = NSTG * STAGE_B;   // 92160 B
    cudaFuncSetAttribute(k_gemm<true>,  cudaFuncAttributeMaxDynamicSharedMemorySize, smem);
    cudaFuncSetAttribute(k_gemm<false>, cudaFuncAttributeMaxDynamicSharedMemorySize, smem);

    k_prep<<<PREPB, 256>>>(W1, W2, u, b1);
    k_scatter<<<(N_EDGES + 255) / 256, 256>>>(ei + N_EDGES);
    k_gather<<<(N_NODES + 7) / 8, 256>>>(x, ea);

    dim3 g1(HIDDEN / BN, (N_NODES + BM - 1) / BM);   // (4, 391)
    k_gemm<true><<<g1, 256, smem>>>(pH, pW1t, nullptr, pUg, bt, nullptr,
                                    (void*)pHid, N_NODES, MLP_K, HIDDEN);
    dim3 g2(NODE_F / BN, (N_NODES + BM - 1) / BM);   // (1, 391)
    k_gemm<false><<<g2, 256, smem>>>(pHid, pW2t, b2, nullptr, nullptr, x,
                                     (void*)out, N_NODES, HIDDEN, NODE_F);
}

// round 12
// speedup vs baseline: 1.0817x; 1.0817x over previous
#include <cuda_runtime.h>
#include <cuda_fp16.h>
#include <cstdint>
#include <cstddef>

#define N_NODES 50000
#define N_EDGES 800000
#define EDGE_F 96
#define NODE_F 256
#define GLOB_F 64
#define HIDDEN 1024
#define MLP_K 544            // K for GEMM1 after hoisting the u-term
#define N_GRAPHS 8
#define CAP 128

// ---------------- scratch (static device globals; no allocations) ------------
// g_cnt starts zeroed (.bss) and is re-zeroed by k_gather each run.
__device__ int    g_cnt[N_NODES];
__device__ int    g_bucket[N_NODES * CAP];
__device__ __half g_h[(size_t)N_NODES * MLP_K];      // fp16 MLP input (544 feats)
__device__ __half g_hid[(size_t)N_NODES * HIDDEN];   // fp16 hidden
__device__ __half g_w1t[HIDDEN * MLP_K];             // W1[0:544]^T fp16  [n][k]
__device__ __half g_w2t[NODE_F * HIDDEN];            // W2^T fp16  [n][k]
__device__ float  g_ug[N_GRAPHS * HIDDEN];           // b1 + u @ W1[544:608]

// ---------------- merged scatter + weight-prep kernel ------------------------
// blocks [0, SCB): edge scatter ; [SCB, SCB+544): W1^T tiles ;
// [SCB+544, SCB+800): W2^T tiles ; [SCB+800, SCB+832): ug table
#define SCB 3125                       // ceil(800000/256)
#define PREPB (SCB + 832)

__global__ void k_scatter_prep(const int* __restrict__ col,
                               const float* __restrict__ W1,
                               const float* __restrict__ W2,
                               const float* __restrict__ u,
                               const float* __restrict__ b1) {
    int b = blockIdx.x;
    int t = threadIdx.x;
    if (b < SCB) {                              // ---- edge scatter
        int e = b * 256 + t;
        if (e >= N_EDGES) return;
        int c = col[e];
        int p = atomicAdd(&g_cnt[c], 1);
        if (p < CAP) g_bucket[c * CAP + p] = e;
        return;
    }
    int b2 = b - SCB;
    if (b2 < 800) {                             // ---- tiled weight transposes
        __shared__ float tile[32][33];
        bool isW1 = (b2 < 544);
        int tb = isW1 ? b2 : (b2 - 544);
        int ntiles_n = isW1 ? 32 : 8;
        int K = isW1 ? MLP_K : HIDDEN;
        int N = isW1 ? HIDDEN : NODE_F;
        const float* W = isW1 ? W1 : W2;
        __half* Wt = isW1 ? g_w1t : g_w2t;
        int k0 = (tb / ntiles_n) * 32;
        int n0 = (tb % ntiles_n) * 32;
        int r = t >> 5, c = t & 31;
#pragma unroll
        for (int p = 0; p < 4; p++)             // read coalesced in n
            tile[r + 8 * p][c] = W[(size_t)(k0 + r + 8 * p) * N + n0 + c];
        __syncthreads();
        int r2 = t >> 4, c2 = (t & 15) * 2;     // write coalesced in k (half2)
#pragma unroll
        for (int p = 0; p < 2; p++) {
            int nn = r2 + 16 * p;
            __half2 v = __floats2half2_rn(tile[c2][nn], tile[c2 + 1][nn]);
            *(__half2*)(Wt + (size_t)(n0 + nn) * K + k0 + c2) = v;
        }
        return;
    }
    {                                           // ---- ug table
        int idx = (b2 - 800) * 256 + t;
        int g = idx >> 10, n = idx & (HIDDEN - 1);
        float s = b1[n];
#pragma unroll 8
        for (int j = 0; j < GLOB_F; j++)
            s += u[g * GLOB_F + j] * W1[(size_t)(MLP_K + j) * HIDDEN + n];
        g_ug[idx] = s;
    }
}

// warp-per-node gather-reduce with 8-wide index prefetch; fp16 h row output.
// Also resets g_cnt[node] = 0 for the next graph replay.
__global__ void k_gather(const float* __restrict__ x, const float* __restrict__ ea) {
    int node = blockIdx.x * 8 + (threadIdx.x >> 5);
    if (node >= N_NODES) return;
    int lane = threadIdx.x & 31;
    int deg = g_cnt[node];
    if (deg > CAP) deg = CAP;
    const float NEG = __int_as_float(0xff800000);
    float s0 = 0.f, s1 = 0.f, s2 = 0.f;
    float m0 = NEG, m1 = NEG, m2 = NEG;
    const int* bk = g_bucket + node * CAP;

    int j = 0;
    for (; j + 8 <= deg; j += 8) {
        const float* p[8];
#pragma unroll
        for (int q = 0; q < 8; q++) p[q] = ea + (size_t)bk[j + q] * EDGE_F;
        float v0[8], v1[8], v2[8];
#pragma unroll
        for (int q = 0; q < 8; q++) {
            v0[q] = p[q][lane]; v1[q] = p[q][lane + 32]; v2[q] = p[q][lane + 64];
        }
#pragma unroll
        for (int q = 0; q < 8; q++) {
            s0 += v0[q]; m0 = fmaxf(m0, v0[q]);
            s1 += v1[q]; m1 = fmaxf(m1, v1[q]);
            s2 += v2[q]; m2 = fmaxf(m2, v2[q]);
        }
    }
    for (; j < deg; j++) {
        const float* r = ea + (size_t)bk[j] * EDGE_F;
        float v0 = r[lane], v1 = r[lane + 32], v2 = r[lane + 64];
        s0 += v0; m0 = fmaxf(m0, v0);
        s1 += v1; m1 = fmaxf(m1, v1);
        s2 += v2; m2 = fmaxf(m2, v2);
    }
    if (deg == 0) { m0 = 0.f; m1 = 0.f; m2 = 0.f; }
    float inv = deg ? 1.f / (float)deg : 0.f;

    __half* h = g_h + (size_t)node * MLP_K;
    const float* xr = x + (size_t)node * NODE_F;
#pragma unroll
    for (int i = 0; i < 4; i++) {               // x copy: float2 -> half2
        float2 v = *(const float2*)(xr + 2 * lane + 64 * i);
        *(__half2*)(h + 2 * lane + 64 * i) = __floats2half2_rn(v.x, v.y);
    }
    h[256 + lane] = __float2half_rn(s0);
    h[288 + lane] = __float2half_rn(s1);
    h[320 + lane] = __float2half_rn(s2);
    h[352 + lane] = __float2half_rn(m0);
    h[384 + lane] = __float2half_rn(m1);
    h[416 + lane] = __float2half_rn(m2);
    h[448 + lane] = __float2half_rn(s0 * inv);
    h[480 + lane] = __float2half_rn(s1 * inv);
    h[512 + lane] = __float2half_rn(s2 * inv);
    if (lane == 0) g_cnt[node] = 0;             // reset for next replay
}

// ---------------- fp16 GEMM (mma.sync m16n8k16 + ldmatrix, 3-stage cp.async) -
#define BM 128
#define BN 128
#define BK 32
#define ROWB 80
#define TILE_B (BM * ROWB)          // 10240 B per operand tile
#define STAGE_B (2 * TILE_B)        // 20480 B per stage
#define NSTG 3

__device__ __forceinline__ void cp16(uint32_t dst, const void* src, int sz) {
    asm volatile("cp.async.cg.shared.global [%0], [%1], 16, %2;\n"
                 :: "r"(dst), "l"(src), "r"(sz));
}

__device__ __forceinline__ void ldsm4(uint32_t* r, uint32_t addr) {
    asm volatile("ldmatrix.sync.aligned.m8n8.x4.shared.b16 {%0,%1,%2,%3}, [%4];"
                 : "=r"(r[0]), "=r"(r[1]), "=r"(r[2]), "=r"(r[3]) : "r"(addr));
}

template <bool FIRST>
__global__ void __launch_bounds__(256, 2)
k_gemm(const __half* __restrict__ A, const __half* __restrict__ Bw,
       const float* __restrict__ bias,           // GEMM2: b2 ; GEMM1: unused
       const float* __restrict__ ug,             // GEMM1: per-graph table
       const int* __restrict__ batch,            // GEMM1: node -> graph
       const float* __restrict__ resid,
       void* __restrict__ Cp, int M, int K, int N) {
    extern __shared__ char smc[];
    uint32_t smb = (uint32_t)__cvta_generic_to_shared(smc);
    int tid = threadIdx.x;
    int warp = tid >> 5, lane = tid & 31;
    int bm = blockIdx.y * BM;
    int bn = blockIdx.x * BN;
    int KT = K / BK;

    auto load = [&](int st, int kb) {
        uint32_t ab = smb + st * STAGE_B;
        uint32_t bb = ab + TILE_B;
#pragma unroll
        for (int i = 0; i < 2; i++) {
            int id = tid + i * 256;
            int r = id >> 2, c = id & 3;
            int gr = bm + r;
            const __half* srcA = A + (size_t)((gr < M) ? gr : 0) * K + kb * BK + c * 8;
            cp16(ab + r * ROWB + c * 16, srcA, (gr < M) ? 16 : 0);
            const __half* srcB = Bw + (size_t)(bn + r) * K + kb * BK + c * 8;
            cp16(bb + r * ROWB + c * 16, srcB, 16);
        }
    };

    load(0, 0);
    asm volatile("cp.async.commit_group;\n");
    load(1, 1);
    asm volatile("cp.async.commit_group;\n");

    float acc[4][4][4];
#pragma unroll
    for (int a = 0; a < 4; a++)
#pragma unroll
        for (int b = 0; b < 4; b++)
#pragma unroll
            for (int c = 0; c < 4; c++) acc[a][b][c] = 0.f;

    int wm = (warp & 1) * 64, wn = (warp >> 1) * 32;
    int a_m = (lane & 7) + ((lane >> 3) & 1) * 8;
    int a_k8 = (lane >> 4) * 8;
    int b_n = lane & 7;
    int b_k8 = (lane >> 3) * 8;

    for (int kt = 0; kt < KT; kt++) {
        asm volatile("cp.async.wait_group 1;\n");
        __syncthreads();
        uint32_t ab = smb + (kt % NSTG) * STAGE_B;
        uint32_t bb = ab + TILE_B;

        uint32_t bF[4][4];
#pragma unroll
        for (int nt = 0; nt < 4; nt++)
            ldsm4(bF[nt], bb + (wn + nt * 8 + b_n) * ROWB + b_k8 * 2);

#pragma unroll
        for (int ks = 0; ks < 2; ks++) {
            uint32_t aF[4][4];
#pragma unroll
            for (int mt = 0; mt < 4; mt++)
                ldsm4(aF[mt], ab + (wm + mt * 16 + a_m) * ROWB + (ks * 16 + a_k8) * 2);
#pragma unroll
            for (int mt = 0; mt < 4; mt++)
#pragma unroll
                for (int nt = 0; nt < 4; nt++)
                    asm volatile(
                        "mma.sync.aligned.m16n8k16.row.col.f32.f16.f16.f32 "
                        "{%0,%1,%2,%3},{%4,%5,%6,%7},{%8,%9},{%0,%1,%2,%3};\n"
                        : "+f"(acc[mt][nt][0]), "+f"(acc[mt][nt][1]),
                          "+f"(acc[mt][nt][2]), "+f"(acc[mt][nt][3])
                        : "r"(aF[mt][0]), "r"(aF[mt][1]), "r"(aF[mt][2]), "r"(aF[mt][3]),
                          "r"(bF[nt][2 * ks]), "r"(bF[nt][2 * ks + 1]));
        }
        if (kt + 2 < KT) load((kt + 2) % NSTG, kt + 2);
        asm volatile("cp.async.commit_group;\n");
    }

    // ---------------- epilogue ----------------
    int lr = lane >> 2, lc = lane & 3;
#pragma unroll
    for (int mt = 0; mt < 4; mt++) {
        int rb = bm + wm + mt * 16 + lr;
        int row0 = rb, row1 = rb + 8;
        int g0 = 0, g1 = 0;
        if (FIRST) {
            g0 = (row0 < M) ? batch[row0] : 0;
            g1 = (row1 < M) ? batch[row1] : 0;
        }
#pragma unroll
        for (int nt = 0; nt < 4; nt++) {
            int cb = bn + wn + nt * 8 + 2 * lc;
            if (FIRST) {
                __half* C = (__half*)Cp;
                if (row0 < M) {
                    float2 t = *(const float2*)(ug + g0 * HIDDEN + cb);
                    float v0 = fmaxf(acc[mt][nt][0] + t.x, 0.f);
                    float v1 = fmaxf(acc[mt][nt][1] + t.y, 0.f);
                    *(__half2*)(C + (size_t)row0 * N + cb) = __floats2half2_rn(v0, v1);
                }
                if (row1 < M) {
                    float2 t = *(const float2*)(ug + g1 * HIDDEN + cb);
                    float v2 = fmaxf(acc[mt][nt][2] + t.x, 0.f);
                    float v3 = fmaxf(acc[mt][nt][3] + t.y, 0.f);
                    *(__half2*)(C + (size_t)row1 * N + cb) = __floats2half2_rn(v2, v3);
                }
            } else {
                float bx = bias[cb], by = bias[cb + 1];
                float* C = (float*)Cp;
                if (row0 < M) {
                    C[(size_t)row0 * N + cb]     = acc[mt][nt][0] + bx + resid[(size_t)row0 * N + cb];
                    C[(size_t)row0 * N + cb + 1] = acc[mt][nt][1] + by + resid[(size_t)row0 * N + cb + 1];
                }
                if (row1 < M) {
                    C[(size_t)row1 * N + cb]     = acc[mt][nt][2] + bx + resid[(size_t)row1 * N + cb];
                    C[(size_t)row1 * N + cb + 1] = acc[mt][nt][3] + by + resid[(size_t)row1 * N + cb + 1];
                }
            }
        }
    }
}

// ---------------- launch ------------------------------------------------------
extern "C" void kernel_launch(void* const* d_in, const int* in_sizes, int n_in,
                              void* d_out, int out_size) {
    const float* x  = (const float*)d_in[0];
    const float* ea = (const float*)d_in[1];
    const float* u  = (const float*)d_in[2];
    const float* W1 = (const float*)d_in[3];
    const float* b1 = (const float*)d_in[4];
    const float* W2 = (const float*)d_in[5];
    const float* b2 = (const float*)d_in[6];
    const int*   ei = (const int*)d_in[7];   // [2, N_EDGES] int32
    const int*   bt = (const int*)d_in[8];
    float* out = (float*)d_out;

    __half *pH, *pHid, *pW1t, *pW2t;
    float* pUg;
    cudaGetSymbolAddress((void**)&pH, g_h);
    cudaGetSymbolAddress((void**)&pHid, g_hid);
    cudaGetSymbolAddress((void**)&pW1t, g_w1t);
    cudaGetSymbolAddress((void**)&pW2t, g_w2t);
    cudaGetSymbolAddress((void**)&pUg, g_ug);

    const int smem = NSTG * STAGE_B;   // 61440 B
    cudaFuncSetAttribute(k_gemm<true>,  cudaFuncAttributeMaxDynamicSharedMemorySize, smem);
    cudaFuncSetAttribute(k_gemm<false>, cudaFuncAttributeMaxDynamicSharedMemorySize, smem);

    k_scatter_prep<<<PREPB, 256>>>(ei + N_EDGES, W1, W2, u, b1);
    k_gather<<<(N_NODES + 7) / 8, 256>>>(x, ea);

    dim3 g1(HIDDEN / BN, (N_NODES + BM - 1) / BM);   // (8, 391)
    k_gemm<true><<<g1, 256, smem>>>(pH, pW1t, nullptr, pUg, bt, nullptr,
                                    (void*)pHid, N_NODES, MLP_K, HIDDEN);
    dim3 g2(NODE_F / BN, (N_NODES + BM - 1) / BM);   // (2, 391)
    k_gemm<false><<<g2, 256, smem>>>(pHid, pW2t, b2, nullptr, nullptr, x,
                                     (void*)out, N_NODES, HIDDEN, NODE_F);
}